// round 3
// baseline (speedup 1.0000x reference)
#include <cuda_runtime.h>
#include <cuda_bf16.h>

// LinearRationalSpline forward.
// inputs:  [16384, 64] f32          (N = 1048576)
// params:  [16384, 64, 63] f32      (w[16], h[16], d[15], lam[16])
// out:     [2*N] f32  -> out[0:N] = outputs, out[N:2N] = logabsdet
//
// Strategy: stage only w+h (32 floats/elem) into shared, coalesced.
// d0/d1/lam (3 of 31 floats) are loaded directly from global after the bin
// index is known -> ~11% less DRAM traffic. Small register footprint
// (single cw[16] array, two-pass heights softmax) -> 48 warps/SM.

#define TPB 128
#define NBINS 16
#define SSTRIDE 33   // 32 staged floats + 1 pad -> conflict-free stride

__device__ __forceinline__ float softplus_f(float v) {
    return fmaxf(v, 0.0f) + __logf(1.0f + __expf(-fabsf(v)));
}

__global__ __launch_bounds__(TPB, 12)
void lrs_kernel(const float* __restrict__ inputs,
                const float* __restrict__ params,
                float* __restrict__ out,
                int N)
{
    constexpr float BOUND = 3.0f;
    constexpr float MBW   = 0.001f;
    constexpr float MBH   = 0.001f;
    constexpr float MIND  = 0.001f;
    constexpr float MINL  = 0.025f;
    constexpr float EPSV  = 1e-6f;

    __shared__ float sp[TPB * SSTRIDE];

    const int tid  = threadIdx.x;
    const int lane = tid & 31;
    const int wid  = tid >> 5;
    const long long blockElem = (long long)blockIdx.x * TPB;
    const int remaining = N - (int)blockElem;
    const int nElem = remaining < TPB ? remaining : TPB;

    // ---- stage w+h (first 32 floats of each element) coalesced ----
    // warp loads one element's 32 floats per iteration (lane-contiguous)
    if (nElem == TPB) {
        #pragma unroll
        for (int it = 0; it < TPB / 4; it++) {
            int q = it * 4 + wid;                       // local element
            sp[q * SSTRIDE + lane] = params[(blockElem + q) * 63 + lane];
        }
    } else {
        for (int it = 0; it < TPB / 4; it++) {
            int q = it * 4 + wid;
            if (q < nElem)
                sp[q * SSTRIDE + lane] = params[(blockElem + q) * 63 + lane];
        }
    }
    __syncthreads();

    const int e = (int)blockElem + tid;
    if (e >= N) return;

    const float x = inputs[e];
    const float* __restrict__ p = sp + tid * SSTRIDE;

    // ---- widths softmax cumsum (cw kept in registers) ----
    float wmax = p[0];
    #pragma unroll
    for (int i = 1; i < NBINS; i++) wmax = fmaxf(wmax, p[i]);
    float cw[NBINS];
    {
        float s = 0.0f;
        #pragma unroll
        for (int i = 0; i < NBINS; i++) { s += __expf(p[i] - wmax); cw[i] = s; }
    }
    const float Aw = 6.0f * (1.0f - 16.0f * MBW) * __frcp_rn(cw[NBINS - 1]);

    // ---- bin search + capture knot_b (cumw) and knot_{b+1} (wnext) ----
    // knot_i = Aw*cw[i-1] + 6*MBW*i - BOUND  (i=1..15), knot_16 = BOUND
    int cnt = 0;
    float cumw  = -BOUND;
    float wnext =  BOUND;
    #pragma unroll
    for (int i = 1; i <= 15; i++) {
        float kv = fmaf(Aw, cw[i - 1], 6.0f * MBW * (float)i - BOUND);
        bool c = (kv + EPSV) <= x;
        cnt  += c ? 1 : 0;
        cumw  = c ? kv : cumw;
        wnext = (!c && wnext == BOUND) ? kv : wnext;   // first false knot
    }
    cnt += ((BOUND + EPSV) <= x) ? 1 : 0;
    const int b = cnt > 15 ? 15 : cnt;

    const float input_widths = wnext - cumw;

    // ---- heights softmax: pass1 max+sum, pass2 capture cumsum at b-1,b ----
    float hmax = p[16];
    #pragma unroll
    for (int i = 1; i < NBINS; i++) hmax = fmaxf(hmax, p[16 + i]);
    float hsum = 0.0f;
    #pragma unroll
    for (int i = 0; i < NBINS; i++) hsum += __expf(p[16 + i] - hmax);
    const float Ah = 6.0f * (1.0f - 16.0f * MBH) * __frcp_rn(hsum);

    float c0 = 0.0f, c1 = 0.0f;
    {
        float s = 0.0f;
        #pragma unroll
        for (int i = 0; i < NBINS; i++) {
            s += __expf(p[16 + i] - hmax);
            c0 = (i == b - 1) ? s : c0;
            c1 = (i == b)     ? s : c1;
        }
    }
    const float ya  = (b == 0)  ? -BOUND : fmaf(Ah, c0, 6.0f * MBH * (float)b - BOUND);
    const float ykn = (b == 15) ?  BOUND : fmaf(Ah, c1, 6.0f * MBH * (float)(b + 1) - BOUND);
    const float input_heights = ykn - ya;
    const float yb = input_heights + ya;

    // ---- scattered global loads: derivatives at b-1,b and lambda at b ----
    const long long gbase = (long long)e * 63;
    const float d0r  = params[gbase + 32 + (b > 0  ? b - 1 : 0)];
    const float d1r  = params[gbase + 32 + (b < 15 ? b     : 14)];
    const float lraw = params[gbase + 47 + b];

    const float d0 = (b == 0)  ? (1.0f - MIND) : (MIND + softplus_f(d0r));
    const float d1 = (b == 15) ? (1.0f - MIND) : (MIND + softplus_f(d1r));

    const float sig = __frcp_rn(1.0f + __expf(-lraw));
    const float lam = fmaf(1.0f - 2.0f * MINL, sig, MINL);

    // ---- rational spline ----
    const float wbv = __fsqrt_rn(__fdividef(d0, d1));
    const float lwb = lam * wbv;
    const float delta = __fdividef(input_heights, input_widths);
    const float wc = __fdividef(fmaf(lam, d0, (wbv - lwb) * d1), delta);
    const float l1 = 1.0f - lam;
    const float yc = __fdividef(lwb * yb + l1 * ya, l1 + lwb);

    const float theta = __fdividef(x - cumw, input_widths);
    const bool ind = theta <= lam;
    const float ltheta = lam - theta;

    const float wcyc = wc * yc;
    const float wcyctheta = wcyc * theta;
    const float wbyb = wbv * yb;
    const float num = ind ? fmaf(ya, ltheta, wcyctheta)
                          : (wcyc - wcyctheta) - wbyb * ltheta;
    const float wctheta = wc * theta;
    const float den = ind ? (wctheta + ltheta)
                          : (wc - wctheta) - wbv * ltheta;
    const float outv = __fdividef(num, den);

    const float dnum = __fdividef(
        wc * (ind ? lam * (yc - ya) : (wbv - lwb) * (yb - yc)),
        input_widths);
    const float lad = __logf(dnum) - 2.0f * __logf(fabsf(den));

    const bool outside = (x < -BOUND) || (x > BOUND);
    out[e]     = outside ? x    : outv;
    out[N + e] = outside ? 0.0f : lad;
}

extern "C" void kernel_launch(void* const* d_in, const int* in_sizes, int n_in,
                              void* d_out, int out_size) {
    const float* inputs = (const float*)d_in[0];
    const float* params = (const float*)d_in[1];
    float* out = (float*)d_out;
    const int N = in_sizes[0];
    const int grid = (N + TPB - 1) / TPB;
    lrs_kernel<<<grid, TPB>>>(inputs, params, out, N);
}

// round 4
// speedup vs baseline: 1.3943x; 1.3943x over previous
#include <cuda_runtime.h>
#include <cuda_bf16.h>
#include <cstdint>

// LinearRationalSpline forward — persistent TMA-pipelined version.
// inputs:  [16384, 64] f32          (N = 1048576)
// params:  [16384, 64, 63] f32
// out:     [2*N] f32
//
// Persistent grid (3 blocks/SM), each block double-buffers tiles of 128
// elements via cp.async.bulk (params 32256 B + inputs 512 B per tile) with
// mbarrier completion, so DRAM streams continuously while warps compute.

#define TPB   128
#define TILE  128
#define NBINS 16

#define STAGE_FLOATS (TILE * 63)
#define PARAMS_BYTES (STAGE_FLOATS * 4)          // 32256
#define X_BYTES      (TILE * 4)                  // 512
#define STAGE_BYTES  (PARAMS_BYTES + X_BYTES)    // 32768
#define BUF_OFF      64                          // mbarriers live in [0,16)
#define SMEM_TOTAL   (BUF_OFF + 2 * STAGE_BYTES) // 65600

__device__ __forceinline__ uint32_t smem_u32(const void* p) {
    uint32_t a;
    asm("{ .reg .u64 t; cvta.to.shared.u64 t, %1; cvt.u32.u64 %0, t; }"
        : "=r"(a) : "l"(p));
    return a;
}

__device__ __forceinline__ void mbar_init(uint32_t mbar, uint32_t cnt) {
    asm volatile("mbarrier.init.shared.b64 [%0], %1;" :: "r"(mbar), "r"(cnt) : "memory");
}
__device__ __forceinline__ void mbar_expect_tx(uint32_t mbar, uint32_t bytes) {
    asm volatile("mbarrier.arrive.expect_tx.shared.b64 _, [%0], %1;"
                 :: "r"(mbar), "r"(bytes) : "memory");
}
__device__ __forceinline__ void mbar_wait(uint32_t mbar, uint32_t parity) {
    asm volatile(
        "{\n\t"
        ".reg .pred P1;\n\t"
        "WAIT_%=:\n\t"
        "mbarrier.try_wait.parity.acquire.cta.shared::cta.b64 P1, [%0], %1, 0x989680;\n\t"
        "@P1 bra.uni DONE_%=;\n\t"
        "bra.uni WAIT_%=;\n\t"
        "DONE_%=:\n\t"
        "}" :: "r"(mbar), "r"(parity) : "memory");
}
__device__ __forceinline__ void bulk_g2s(uint32_t dst, const void* src,
                                         uint32_t bytes, uint32_t mbar) {
    asm volatile(
        "cp.async.bulk.shared::cluster.global.mbarrier::complete_tx::bytes "
        "[%0], [%1], %2, [%3];"
        :: "r"(dst), "l"(src), "r"(bytes), "r"(mbar) : "memory");
}
__device__ __forceinline__ void fence_async() {
    asm volatile("fence.proxy.async.shared::cta;" ::: "memory");
}

__device__ __forceinline__ float softplus_f(float v) {
    return fmaxf(v, 0.0f) + __logf(1.0f + __expf(-fabsf(v)));
}

// issue both bulk copies for a tile into buffer `bsel` (full tiles only)
__device__ __forceinline__ void issue_tile(uint32_t sbase, int bsel,
                                           const float* params, const float* inputs,
                                           long long tile) {
    uint32_t mbar = sbase + bsel * 8;
    uint32_t dst  = sbase + BUF_OFF + bsel * STAGE_BYTES;
    mbar_expect_tx(mbar, STAGE_BYTES);
    bulk_g2s(dst, params + tile * STAGE_FLOATS, PARAMS_BYTES, mbar);
    bulk_g2s(dst + PARAMS_BYTES, inputs + tile * TILE, X_BYTES, mbar);
}

__global__ __launch_bounds__(TPB)
void lrs_kernel(const float* __restrict__ inputs,
                const float* __restrict__ params,
                float* __restrict__ out,
                int N, int numTiles)
{
    constexpr float BOUND = 3.0f;
    constexpr float MBW   = 0.001f;
    constexpr float MBH   = 0.001f;
    constexpr float MIND  = 0.001f;
    constexpr float MINL  = 0.025f;
    constexpr float EPSV  = 1e-6f;

    extern __shared__ char smem[];
    const uint32_t sbase = smem_u32(smem);
    const int tid = threadIdx.x;

    if (tid == 0) {
        mbar_init(sbase + 0, 1);
        mbar_init(sbase + 8, 1);
        fence_async();
    }
    __syncthreads();

    const long long step = gridDim.x;

    // prologue: prefetch my first two tiles (full tiles only)
    if (tid == 0) {
        long long t0 = blockIdx.x;
        long long t1 = blockIdx.x + step;
        if (t0 < numTiles && (t0 + 1) * TILE <= N)
            issue_tile(sbase, 0, params, inputs, t0);
        if (t1 < numTiles && (t1 + 1) * TILE <= N)
            issue_tile(sbase, 1, params, inputs, t1);
    }

    int phase0 = 0, phase1 = 0;
    int bsel = 0;

    for (long long tile = blockIdx.x; tile < numTiles; tile += step) {
        const long long e0 = tile * TILE;
        const int elems = (N - e0) < TILE ? (int)(N - e0) : TILE;
        float* bufp = (float*)(smem + BUF_OFF + bsel * STAGE_BYTES);
        float* bufx = bufp + STAGE_FLOATS;

        if (elems == TILE) {
            if (bsel == 0) { mbar_wait(sbase + 0, phase0); phase0 ^= 1; }
            else           { mbar_wait(sbase + 8, phase1); phase1 ^= 1; }
        } else {
            // partial tail tile: direct staging (rare / never for N%128==0)
            for (int i = tid; i < elems * 63; i += TPB)
                bufp[i] = params[e0 * 63 + i];
            if (tid < elems) bufx[tid] = inputs[e0 + tid];
            __syncthreads();
        }

        if (tid < elems) {
            const float x = bufx[tid];
            const float* __restrict__ p = bufp + tid * 63;  // stride 63: conflict-free

            // widths softmax cumsum
            float wmax = p[0];
            #pragma unroll
            for (int i = 1; i < NBINS; i++) wmax = fmaxf(wmax, p[i]);
            float cw[NBINS];
            {
                float s = 0.0f;
                #pragma unroll
                for (int i = 0; i < NBINS; i++) { s += __expf(p[i] - wmax); cw[i] = s; }
            }
            const float Aw = 6.0f * (1.0f - 16.0f * MBW) * __frcp_rn(cw[NBINS - 1]);

            // heights softmax cumsum
            float hmax = p[16];
            #pragma unroll
            for (int i = 1; i < NBINS; i++) hmax = fmaxf(hmax, p[16 + i]);
            float ch[NBINS];
            {
                float s = 0.0f;
                #pragma unroll
                for (int i = 0; i < NBINS; i++) { s += __expf(p[16 + i] - hmax); ch[i] = s; }
            }
            const float Ah = 6.0f * (1.0f - 16.0f * MBH) * __frcp_rn(ch[NBINS - 1]);

            // bin search on width knots, capturing knot_b / knot_{b+1}
            int cnt = 0;
            float cumw  = -BOUND;
            float wnext =  BOUND;
            bool found = false;
            #pragma unroll
            for (int i = 1; i <= 15; i++) {
                float kv = fmaf(Aw, cw[i - 1], 6.0f * MBW * (float)i - BOUND);
                bool c = (kv + EPSV) <= x;
                cnt  += c ? 1 : 0;
                cumw  = c ? kv : cumw;
                if (!c && !found) { wnext = kv; found = true; }
            }
            cnt += ((BOUND + EPSV) <= x) ? 1 : 0;
            const int b = cnt > 15 ? 15 : cnt;

            const float input_widths = wnext - cumw;

            // select cum-heights at b-1, b
            float c0 = 0.0f, c1 = ch[0];
            #pragma unroll
            for (int i = 1; i < NBINS; i++) {
                bool g = (b >= i);
                c0 = g ? ch[i - 1] : c0;
                c1 = g ? ch[i]     : c1;
            }
            const float ya  = (b == 0)  ? -BOUND : fmaf(Ah, c0, 6.0f * MBH * (float)b - BOUND);
            const float ykn = (b == 15) ?  BOUND : fmaf(Ah, c1, 6.0f * MBH * (float)(b + 1) - BOUND);
            const float input_heights = ykn - ya;
            const float yb = input_heights + ya;

            // derivatives + lambda from smem (dynamic LDS)
            const float d0r  = p[32 + (b > 0  ? b - 1 : 0)];
            const float d1r  = p[32 + (b < 15 ? b     : 14)];
            const float lraw = p[47 + b];

            const float d0 = (b == 0)  ? (1.0f - MIND) : (MIND + softplus_f(d0r));
            const float d1 = (b == 15) ? (1.0f - MIND) : (MIND + softplus_f(d1r));

            const float sig = __frcp_rn(1.0f + __expf(-lraw));
            const float lam = fmaf(1.0f - 2.0f * MINL, sig, MINL);

            // rational spline
            const float wbv = __fsqrt_rn(__fdividef(d0, d1));
            const float lwb = lam * wbv;
            const float delta = __fdividef(input_heights, input_widths);
            const float wc = __fdividef(fmaf(lam, d0, (wbv - lwb) * d1), delta);
            const float l1 = 1.0f - lam;
            const float yc = __fdividef(lwb * yb + l1 * ya, l1 + lwb);

            const float theta = __fdividef(x - cumw, input_widths);
            const bool ind = theta <= lam;
            const float ltheta = lam - theta;

            const float wcyc = wc * yc;
            const float wcyctheta = wcyc * theta;
            const float wbyb = wbv * yb;
            const float num = ind ? fmaf(ya, ltheta, wcyctheta)
                                  : (wcyc - wcyctheta) - wbyb * ltheta;
            const float wctheta = wc * theta;
            const float den = ind ? (wctheta + ltheta)
                                  : (wc - wctheta) - wbv * ltheta;
            const float outv = __fdividef(num, den);

            const float dnum = __fdividef(
                wc * (ind ? lam * (yc - ya) : (wbv - lwb) * (yb - yc)),
                input_widths);
            const float lad = __logf(dnum) - 2.0f * __logf(fabsf(den));

            const bool outside = (x < -BOUND) || (x > BOUND);
            const int e = (int)e0 + tid;
            out[e]     = outside ? x    : outv;
            out[N + e] = outside ? 0.0f : lad;
        }

        __syncthreads();   // all warps done reading this buffer

        // refill this buffer with tile + 2*step
        long long nt = tile + 2 * step;
        if (tid == 0 && nt < numTiles && (nt + 1) * TILE <= N) {
            fence_async();  // order prior generic smem reads before async writes
            issue_tile(sbase, bsel, params, inputs, nt);
        }
        bsel ^= 1;
    }
}

extern "C" void kernel_launch(void* const* d_in, const int* in_sizes, int n_in,
                              void* d_out, int out_size) {
    const float* inputs = (const float*)d_in[0];
    const float* params = (const float*)d_in[1];
    float* out = (float*)d_out;
    const int N = in_sizes[0];
    const int numTiles = (N + TILE - 1) / TILE;

    cudaFuncSetAttribute(lrs_kernel,
                         cudaFuncAttributeMaxDynamicSharedMemorySize, SMEM_TOTAL);

    int grid = 148 * 3;                    // persistent: 3 blocks/SM
    if (grid > numTiles) grid = numTiles;
    lrs_kernel<<<grid, TPB, SMEM_TOTAL>>>(inputs, params, out, N, numTiles);
}